// round 4
// baseline (speedup 1.0000x reference)
#include <cuda_runtime.h>
#include <math.h>
#include <stdint.h>

#define Nn 128
#define Tt 256
#define Dd 1024
#define Hh 1024
#define G4 4096
#define Pp 196
#define KK 3072   // [x_t | h | attn]

// ---- device scratch (static: no runtime allocation) ----
__device__ float g_Wf[(size_t)KK * G4];            // permuted [Wx;Wh;Wattn], col j' = u*4+g
__device__ float g_bf[G4];                          // permuted bias
__device__ float g_act[(size_t)Nn * KK];            // [x_t | h | attn] rows
__device__ float g_hnew[Nn * Hh];                   // h_{t+1} ping-pong buffer
__device__ float g_c[Nn * Hh];                      // cell state
__device__ float g_At[(size_t)Nn * Pp * Hh];        // A transposed: [n][p][u]
__device__ float g_sp[Nn][4][Pp];                   // partial scores

__device__ __forceinline__ float2 ffma2(float2 a, float2 b, float2 c) {
    float2 d;
    asm("fma.rn.f32x2 %0, %1, %2, %3;"
        : "=l"(reinterpret_cast<unsigned long long&>(d))
        : "l"(reinterpret_cast<unsigned long long&>(a)),
          "l"(reinterpret_cast<unsigned long long&>(b)),
          "l"(reinterpret_cast<unsigned long long&>(c)));
    return d;
}

// ---- one-time: permute weights to gate-interleaved layout ----
__global__ __launch_bounds__(256) void permute_kernel(
    const float* __restrict__ Wx, const float* __restrict__ Wh,
    const float* __restrict__ Wa, const float* __restrict__ b) {
    size_t total = (size_t)KK * G4;
    size_t stride = (size_t)gridDim.x * blockDim.x;
    for (size_t idx = (size_t)blockIdx.x * blockDim.x + threadIdx.x; idx < total; idx += stride) {
        int k = (int)(idx >> 12);
        int j = (int)(idx & 4095);
        int src = (j & 3) * 1024 + (j >> 2);
        float v;
        if (k < 1024)       v = Wx[(size_t)k * G4 + src];
        else if (k < 2048)  v = Wh[(size_t)(k - 1024) * G4 + src];
        else                v = Wa[(size_t)(k - 2048) * G4 + src];
        g_Wf[idx] = v;
        if (idx < G4) g_bf[idx] = b[src];
    }
}

// ---- one-time: transpose A[n,u,p] -> At[n,p,u] (smem-tiled) ----
__global__ __launch_bounds__(256) void transpose_kernel(const float* __restrict__ A) {
    __shared__ float tile[32][197];
    int n = blockIdx.y;
    int u0 = blockIdx.x * 32;
    const float* src = A + ((size_t)n * Hh + u0) * Pp;
    for (int i = threadIdx.x; i < 32 * Pp; i += 256) {
        int u = i / Pp, p = i - u * Pp;
        tile[u][p] = src[(size_t)u * Pp + p];
    }
    __syncthreads();
    float* dst = g_At + (size_t)n * Pp * Hh + u0;
    for (int i = threadIdx.x; i < 32 * Pp; i += 256) {
        int u = i & 31, p = i >> 5;
        dst[(size_t)p * Hh + u] = tile[u][p];
    }
}

// ---- h0 = c0 = mean_p A[n,u,:] ----
__global__ __launch_bounds__(256) void init_kernel(const float* __restrict__ A) {
    int n = blockIdx.x;
    for (int u = threadIdx.x; u < Hh; u += blockDim.x) {
        const float4* r = (const float4*)(A + ((size_t)n * Hh + u) * Pp);
        float s = 0.f;
#pragma unroll
        for (int i = 0; i < 49; i++) {
            float4 v = r[i];
            s += v.x + v.y + v.z + v.w;
        }
        float m = s * (1.f / 196.f);
        g_hnew[n * Hh + u] = m;   // h0 (scores_kernel commits it into g_act)
        g_c[n * Hh + u] = m;      // c0
    }
}

// ---- scores partial: grid (4, 128) = (u-chunk, n) ----
// commits h (from g_hnew) and x_t chunk into g_act, computes partial scores
__global__ __launch_bounds__(256) void scores_kernel(
    const float* __restrict__ A, const float* __restrict__ x, int t) {
    int uc = blockIdx.x, n = blockIdx.y;
    int tid = threadIdx.x;
    int u0 = uc * 256;
    __shared__ float hsh[256];

    float* actn = g_act + (size_t)n * KK;
    float hv = g_hnew[n * Hh + u0 + tid];
    actn[u0 + tid] = x[((size_t)n * Tt + t) * Dd + u0 + tid];  // x_t chunk
    actn[1024 + u0 + tid] = hv;                                 // commit h chunk
    hsh[tid] = hv;
    __syncthreads();

    if (tid < Pp) {
        const float* ap = A + ((size_t)n * Hh + u0) * Pp + tid;
        float acc = 0.f;
#pragma unroll 8
        for (int u = 0; u < 256; u++) {
            acc += hsh[u] * ap[(size_t)u * Pp];
        }
        g_sp[n][uc][tid] = acc;
    }
}

// ---- attn: combine partials -> softmax -> weighted sum over coalesced At ----
__global__ __launch_bounds__(256) void attnsum_kernel(int t) {
    int uc = blockIdx.x, n = blockIdx.y;
    int tid = threadIdx.x;
    __shared__ __align__(16) float w[Pp];
    __shared__ float red[256];

    float myscore = 0.f, s = -3.4e38f;
    if (tid < Pp) {
        myscore = (g_sp[n][0][tid] + g_sp[n][1][tid] + g_sp[n][2][tid] + g_sp[n][3][tid]) * 0.03125f;
        s = myscore;
    }
    red[tid] = s;
    __syncthreads();
    for (int off = 128; off > 0; off >>= 1) {
        if (tid < off) red[tid] = fmaxf(red[tid], red[tid + off]);
        __syncthreads();
    }
    float mx = red[0];
    __syncthreads();
    float e = (tid < Pp) ? expf(myscore - mx) : 0.f;
    red[tid] = e;
    __syncthreads();
    for (int off = 128; off > 0; off >>= 1) {
        if (tid < off) red[tid] += red[tid + off];
        __syncthreads();
    }
    float inv = 1.f / red[0];
    if (tid < Pp) w[tid] = e * inv;
    __syncthreads();

    int u0 = uc * 256;
    const float* atp = g_At + (size_t)n * Pp * Hh + u0 + tid;
    float acc = 0.f;
#pragma unroll 7
    for (int p = 0; p < Pp; p++) {
        acc += w[p] * atp[(size_t)p * Hh];
    }
    g_act[(size_t)n * KK + 2048 + u0 + tid] = acc;
}

// ---- per-step GEMM (128 x 4096, K=3072) + fused LSTM epilogue ----
// grid 256 (col tiles of 16), 256 threads, thread = 2 rows x 4 cols (one unit's gates)
// reads h_t from g_act, writes h_{t+1} ONLY to g_hnew (race-free ping-pong)
__global__ __launch_bounds__(256, 2) void gates_kernel(float* __restrict__ out, int t) {
    __shared__ __align__(16) float As[32][128];
    __shared__ __align__(16) float Bs[32][16];

    int tid = threadIdx.x;
    int j0 = blockIdx.x * 16;
    int tx = tid & 3;
    int ty = tid >> 2;

    int am = tid & 127;
    int ah = (tid >> 7) * 16;
    int bk = tid >> 3;
    int bc = (tid & 7) * 2;

    float2 c00 = make_float2(0.f, 0.f), c01 = c00, c10 = c00, c11 = c00;

    const float* arow = g_act + (size_t)am * KK + ah;
    const float* bptr = g_Wf + (size_t)bk * G4 + j0 + bc;

    for (int kt = 0; kt < KK / 32; kt++) {
        int k0 = kt * 32;
        float4 ra[4];
#pragma unroll
        for (int i = 0; i < 4; i++) ra[i] = *(const float4*)(arow + k0 + 4 * i);
        float2 rb = *(const float2*)(bptr + (size_t)k0 * G4);
        __syncthreads();
#pragma unroll
        for (int i = 0; i < 4; i++) {
            As[ah + 4 * i + 0][am] = ra[i].x;
            As[ah + 4 * i + 1][am] = ra[i].y;
            As[ah + 4 * i + 2][am] = ra[i].z;
            As[ah + 4 * i + 3][am] = ra[i].w;
        }
        *(float2*)&Bs[bk][bc] = rb;
        __syncthreads();
#pragma unroll
        for (int k = 0; k < 32; k++) {
            float2 a = *(const float2*)&As[k][ty * 2];
            float4 b = *(const float4*)&Bs[k][tx * 4];
            float2 b0 = make_float2(b.x, b.y);
            float2 b1 = make_float2(b.z, b.w);
            c00 = ffma2(make_float2(a.x, a.x), b0, c00);
            c01 = ffma2(make_float2(a.x, a.x), b1, c01);
            c10 = ffma2(make_float2(a.y, a.y), b0, c10);
            c11 = ffma2(make_float2(a.y, a.y), b1, c11);
        }
    }

    int u = (j0 >> 2) + tx;
    float4 bf4 = *(const float4*)&g_bf[j0 + tx * 4];
#pragma unroll
    for (int r = 0; r < 2; r++) {
        int m = ty * 2 + r;
        float ai = (r ? c10.x : c00.x) + bf4.x;
        float af = (r ? c10.y : c00.y) + bf4.y;
        float ao = (r ? c11.x : c01.x) + bf4.z;
        float ag = (r ? c11.y : c01.y) + bf4.w;
        float ig = 1.f / (1.f + expf(-ai));
        float fg = 1.f / (1.f + expf(-af));
        float og = 1.f / (1.f + expf(-ao));
        float gg = tanhf(ag);
        float cn = fg * g_c[m * Hh + u] + ig * gg;
        float hn = og * tanhf(cn);
        g_c[m * Hh + u] = cn;
        g_hnew[m * Hh + u] = hn;       // ping-pong: NOT g_act
        out[((size_t)m * Tt + t) * Hh + u] = hn;
    }
}

extern "C" void kernel_launch(void* const* d_in, const int* in_sizes, int n_in,
                              void* d_out, int out_size) {
    const float* x  = (const float*)d_in[0];
    const float* A  = (const float*)d_in[1];
    const float* Wx = (const float*)d_in[2];
    const float* Wh = (const float*)d_in[3];
    const float* Wa = (const float*)d_in[4];
    const float* b  = (const float*)d_in[5];
    float* out = (float*)d_out;

    permute_kernel<<<2048, 256>>>(Wx, Wh, Wa, b);
    transpose_kernel<<<dim3(32, 128), 256>>>(A);
    init_kernel<<<Nn, 256>>>(A);
    for (int t = 0; t < Tt; t++) {
        scores_kernel<<<dim3(4, Nn), 256>>>(A, x, t);
        attnsum_kernel<<<dim3(4, Nn), 256>>>(t);
        gates_kernel<<<G4 / 16, 256>>>(out, t);
    }
}

// round 6
// speedup vs baseline: 2.3119x; 2.3119x over previous
#include <cuda_runtime.h>
#include <cuda_bf16.h>
#include <math.h>
#include <stdint.h>

#define Nn 128
#define Tt 256
#define Dd 1024
#define Hh 1024
#define G4 4096
#define Pp 196
#define KK 3072   // [x_t | h | attn]

// ================= device scratch (static) =================
__device__ __align__(16) __nv_bfloat16 g_Wfbh[(size_t)G4 * KK];  // Wf^T [j][k] hi
__device__ __align__(16) __nv_bfloat16 g_Wfbl[(size_t)G4 * KK];  // Wf^T [j][k] lo
__device__ __align__(16) __nv_bfloat16 g_acth[(size_t)Nn * KK];  // Act [m][k] hi
__device__ __align__(16) __nv_bfloat16 g_actl[(size_t)Nn * KK];  // Act [m][k] lo
__device__ float g_bf[G4];                    // permuted bias (j' = u*4+g)
__device__ float g_hnewT[Hh * Nn];            // h ping-pong, TRANSPOSED [u][m]
__device__ float g_cT[Hh * Nn];               // cell state, TRANSPOSED [u][m]
__device__ float g_At[(size_t)Nn * Pp * Hh];  // A transposed: [n][p][u]
__device__ float g_sp[Nn][4][Pp];             // partial scores

// ================= helpers (all plain-sm_103-legal) =================
__device__ __forceinline__ uint32_t smem_u32(const void* p) {
    uint32_t a;
    asm("{ .reg .u64 t; cvta.to.shared.u64 t, %1; cvt.u32.u64 %0, t; }" : "=r"(a) : "l"(p));
    return a;
}
__device__ __forceinline__ void cp16(uint32_t dst, const void* src) {
    asm volatile("cp.async.cg.shared.global [%0], [%1], 16;" :: "r"(dst), "l"(src));
}
__device__ __forceinline__ void cpcommit() { asm volatile("cp.async.commit_group;" ::: "memory"); }
template <int N> __device__ __forceinline__ void cpwait() {
    asm volatile("cp.async.wait_group %0;" :: "n"(N) : "memory");
}
__device__ __forceinline__ void ldsm_x4(uint32_t& r0, uint32_t& r1, uint32_t& r2, uint32_t& r3,
                                        uint32_t addr) {
    asm volatile("ldmatrix.sync.aligned.m8n8.x4.shared.b16 {%0,%1,%2,%3}, [%4];"
                 : "=r"(r0), "=r"(r1), "=r"(r2), "=r"(r3) : "r"(addr));
}
__device__ __forceinline__ void mma16816(float* d, const uint32_t* a, const uint32_t* b) {
    asm volatile(
        "mma.sync.aligned.m16n8k16.row.col.f32.bf16.bf16.f32 "
        "{%0,%1,%2,%3}, {%4,%5,%6,%7}, {%8,%9}, {%0,%1,%2,%3};"
        : "+f"(d[0]), "+f"(d[1]), "+f"(d[2]), "+f"(d[3])
        : "r"(a[0]), "r"(a[1]), "r"(a[2]), "r"(a[3]), "r"(b[0]), "r"(b[1]));
}
#define SWZ64(o) ((o) ^ (((o) >> 3) & 0x30))

__device__ __forceinline__ void bf16split(float v, __nv_bfloat16* hi, __nv_bfloat16* lo) {
    __nv_bfloat16 h = __float2bfloat16(v);
    *hi = h;
    *lo = __float2bfloat16(v - __bfloat162float(h));
}

// ================= one-time: permute + split weights to [j][k] bf16 =================
__global__ __launch_bounds__(256) void permute_kernel(
    const float* __restrict__ Wx, const float* __restrict__ Wh,
    const float* __restrict__ Wa, const float* __restrict__ b) {
    size_t total = (size_t)G4 * KK;
    size_t stride = (size_t)gridDim.x * blockDim.x;
    for (size_t idx = (size_t)blockIdx.x * blockDim.x + threadIdx.x; idx < total; idx += stride) {
        int j = (int)(idx / KK);
        int k = (int)(idx - (size_t)j * KK);
        int src = (j & 3) * 1024 + (j >> 2);
        float v;
        if (k < 1024)      v = Wx[(size_t)k * G4 + src];
        else if (k < 2048) v = Wh[(size_t)(k - 1024) * G4 + src];
        else               v = Wa[(size_t)(k - 2048) * G4 + src];
        __nv_bfloat16 hi, lo;
        bf16split(v, &hi, &lo);
        g_Wfbh[idx] = hi;
        g_Wfbl[idx] = lo;
        if (k == 0) g_bf[j] = b[src];
    }
}

// ================= one-time: transpose A[n,u,p] -> At[n,p,u] =================
__global__ __launch_bounds__(256) void transpose_kernel(const float* __restrict__ A) {
    __shared__ float tile[32][197];
    int n = blockIdx.y;
    int u0 = blockIdx.x * 32;
    const float* src = A + ((size_t)n * Hh + u0) * Pp;
    for (int i = threadIdx.x; i < 32 * Pp; i += 256) {
        int u = i / Pp, p = i - u * Pp;
        tile[u][p] = src[(size_t)u * Pp + p];
    }
    __syncthreads();
    float* dst = g_At + (size_t)n * Pp * Hh + u0;
    for (int i = threadIdx.x; i < 32 * Pp; i += 256) {
        int u = i & 31, p = i >> 5;
        dst[(size_t)p * Hh + u] = tile[u][p];
    }
}

// ================= h0 = c0 = mean_p A[n,u,:] =================
__global__ __launch_bounds__(256) void init_kernel(const float* __restrict__ A) {
    int n = blockIdx.x;
    for (int u = threadIdx.x; u < Hh; u += blockDim.x) {
        const float4* r = (const float4*)(A + ((size_t)n * Hh + u) * Pp);
        float s = 0.f;
#pragma unroll
        for (int i = 0; i < 49; i++) {
            float4 v = r[i];
            s += v.x + v.y + v.z + v.w;
        }
        float m = s * (1.f / 196.f);
        g_hnewT[u * Nn + n] = m;
        g_cT[u * Nn + n] = m;
    }
}

// ================= scores partial: grid (4,128); commits x_t + h bf16 splits =================
__global__ __launch_bounds__(256) void scores_kernel(
    const float* __restrict__ A, const float* __restrict__ x, int t) {
    int uc = blockIdx.x, n = blockIdx.y;
    int tid = threadIdx.x;
    int u0 = uc * 256;
    __shared__ float hsh[256];

    float hv = g_hnewT[(u0 + tid) * Nn + n];
    float xv = x[((size_t)n * Tt + t) * Dd + u0 + tid];
    __nv_bfloat16 hi, lo;
    bf16split(xv, &hi, &lo);
    g_acth[(size_t)n * KK + u0 + tid] = hi;
    g_actl[(size_t)n * KK + u0 + tid] = lo;
    bf16split(hv, &hi, &lo);
    g_acth[(size_t)n * KK + 1024 + u0 + tid] = hi;
    g_actl[(size_t)n * KK + 1024 + u0 + tid] = lo;
    hsh[tid] = hv;
    __syncthreads();

    if (tid < Pp) {
        const float* ap = A + ((size_t)n * Hh + u0) * Pp + tid;
        float acc = 0.f;
#pragma unroll 8
        for (int u = 0; u < 256; u++) {
            acc += hsh[u] * ap[(size_t)u * Pp];
        }
        g_sp[n][uc][tid] = acc;
    }
}

// ================= attn: softmax + weighted sum; commits attn bf16 split =================
__global__ __launch_bounds__(256) void attnsum_kernel(int t) {
    int uc = blockIdx.x, n = blockIdx.y;
    int tid = threadIdx.x;
    __shared__ __align__(16) float w[Pp];
    __shared__ float red[256];

    float myscore = 0.f, s = -3.4e38f;
    if (tid < Pp) {
        myscore = (g_sp[n][0][tid] + g_sp[n][1][tid] + g_sp[n][2][tid] + g_sp[n][3][tid]) * 0.03125f;
        s = myscore;
    }
    red[tid] = s;
    __syncthreads();
    for (int off = 128; off > 0; off >>= 1) {
        if (tid < off) red[tid] = fmaxf(red[tid], red[tid + off]);
        __syncthreads();
    }
    float mx = red[0];
    __syncthreads();
    float e = (tid < Pp) ? expf(myscore - mx) : 0.f;
    red[tid] = e;
    __syncthreads();
    for (int off = 128; off > 0; off >>= 1) {
        if (tid < off) red[tid] += red[tid + off];
        __syncthreads();
    }
    float inv = 1.f / red[0];
    if (tid < Pp) w[tid] = e * inv;
    __syncthreads();

    int u0 = uc * 256;
    const float* atp = g_At + (size_t)n * Pp * Hh + u0 + tid;
    float acc = 0.f;
#pragma unroll 7
    for (int p = 0; p < Pp; p++) {
        acc += w[p] * atp[(size_t)p * Hh];
    }
    __nv_bfloat16 hi, lo;
    bf16split(acc, &hi, &lo);
    g_acth[(size_t)n * KK + 2048 + u0 + tid] = hi;
    g_actl[(size_t)n * KK + 2048 + u0 + tid] = lo;
}

// ================= gates: mma.sync split-bf16x3 GEMM + fused LSTM =================
// grid 128 (32 cols each), 256 threads (8 warps x 16 rows). K chunks of 32, cp.async
// double buffer. SMEM buffer layout: Ah[0,8K) Al[8K,16K) Bh[16K,18K) Bl[18K,20K).
#define KC 32
#define NCH (KK / KC)   // 96
#define BUFB 20480

__device__ __forceinline__ void load_chunk(int tid, int j0, int c, char* buf) {
    uint32_t sbase = smem_u32(buf);
#pragma unroll
    for (int it = 0; it < 2; it++) {
        int id = tid + it * 256;          // 0..511 : A rows x 4 16B-chunks
        int m = id >> 2, kc = id & 3;
        uint32_t off = SWZ64((uint32_t)m * 64 + (uint32_t)kc * 16);
        size_t gidx = (size_t)m * KK + (size_t)c * KC + kc * 8;
        cp16(sbase + off, g_acth + gidx);
        cp16(sbase + 8192 + off, g_actl + gidx);
    }
    if (tid < 128) {
        int nrow = tid >> 2, kc = tid & 3;
        uint32_t off = SWZ64((uint32_t)nrow * 64 + (uint32_t)kc * 16);
        size_t gidx = (size_t)(j0 + nrow) * KK + (size_t)c * KC + kc * 8;
        cp16(sbase + 16384 + off, g_Wfbh + gidx);
        cp16(sbase + 18432 + off, g_Wfbl + gidx);
    }
    cpcommit();
}

__global__ __launch_bounds__(256) void gates_mma_kernel(float* __restrict__ out, int t) {
    __shared__ __align__(1024) char sm[2][BUFB];
    int tid = threadIdx.x;
    int w = tid >> 5;
    int lane = tid & 31;
    int j0 = blockIdx.x * 32;

    float acc[4][4];
#pragma unroll
    for (int j = 0; j < 4; j++)
#pragma unroll
        for (int r = 0; r < 4; r++) acc[j][r] = 0.f;

    load_chunk(tid, j0, 0, sm[0]);

    for (int c = 0; c < NCH; c++) {
        if (c + 1 < NCH) {
            load_chunk(tid, j0, c + 1, sm[(c + 1) & 1]);
            cpwait<1>();
        } else {
            cpwait<0>();
        }
        __syncthreads();

        uint32_t sbase = smem_u32(sm[c & 1]);
        // A ldmatrix address (this warp's 16 rows)
        int arow = w * 16 + (lane & 15);
#pragma unroll
        for (int ks = 0; ks < 2; ks++) {
            int ak = ks * 16 + ((lane & 16) ? 8 : 0);
            uint32_t aoff = SWZ64((uint32_t)arow * 64 + (uint32_t)ak * 2);
            uint32_t ah[4], al[4];
            ldsm_x4(ah[0], ah[1], ah[2], ah[3], sbase + aoff);
            ldsm_x4(al[0], al[1], al[2], al[3], sbase + 8192 + aoff);

            uint32_t bh[8], bl[8];
            int bk = ks * 16 + ((lane & 8) ? 8 : 0);
#pragma unroll
            for (int jj = 0; jj < 2; jj++) {
                int nrow = jj * 16 + ((lane & 16) ? 8 : 0) + (lane & 7);
                uint32_t boff = SWZ64((uint32_t)nrow * 64 + (uint32_t)bk * 2);
                ldsm_x4(bh[4 * jj], bh[4 * jj + 1], bh[4 * jj + 2], bh[4 * jj + 3],
                        sbase + 16384 + boff);
                ldsm_x4(bl[4 * jj], bl[4 * jj + 1], bl[4 * jj + 2], bl[4 * jj + 3],
                        sbase + 18432 + boff);
            }
#pragma unroll
            for (int j = 0; j < 4; j++) {
                mma16816(acc[j], ah, &bh[2 * j]);
                mma16816(acc[j], ah, &bl[2 * j]);
                mma16816(acc[j], al, &bh[2 * j]);
            }
        }
        __syncthreads();
    }

    // ---- fused LSTM epilogue ----
    int q = lane & 3;
    int rbase = w * 16 + (lane >> 2);
#pragma unroll
    for (int j = 0; j < 4; j++) {
        float e0 = __shfl_xor_sync(0xffffffff, acc[j][0], 1);
        float e1 = __shfl_xor_sync(0xffffffff, acc[j][1], 1);
        float e2 = __shfl_xor_sync(0xffffffff, acc[j][2], 1);
        float e3 = __shfl_xor_sync(0xffffffff, acc[j][3], 1);
        int u = blockIdx.x * 8 + 2 * j + (q >> 1);
        int m;
        float ai, af, ao, ag;
        if ((q & 1) == 0) {
            m = rbase;
            ai = acc[j][0]; af = acc[j][1]; ao = e0; ag = e1;
        } else {
            m = rbase + 8;
            ai = e2; af = e3; ao = acc[j][2]; ag = acc[j][3];
        }
        float4 bb = *(const float4*)&g_bf[u * 4];
        ai += bb.x; af += bb.y; ao += bb.z; ag += bb.w;
        float ig = 1.f / (1.f + expf(-ai));
        float fg = 1.f / (1.f + expf(-af));
        float og = 1.f / (1.f + expf(-ao));
        float gg = tanhf(ag);
        float cn = fg * g_cT[u * Nn + m] + ig * gg;
        float hn = og * tanhf(cn);
        g_cT[u * Nn + m] = cn;
        g_hnewT[u * Nn + m] = hn;
        out[((size_t)m * Tt + t) * Hh + u] = hn;
    }
}

extern "C" void kernel_launch(void* const* d_in, const int* in_sizes, int n_in,
                              void* d_out, int out_size) {
    const float* x  = (const float*)d_in[0];
    const float* A  = (const float*)d_in[1];
    const float* Wx = (const float*)d_in[2];
    const float* Wh = (const float*)d_in[3];
    const float* Wa = (const float*)d_in[4];
    const float* b  = (const float*)d_in[5];
    float* out = (float*)d_out;

    permute_kernel<<<2048, 256>>>(Wx, Wh, Wa, b);
    transpose_kernel<<<dim3(32, 128), 256>>>(A);
    init_kernel<<<Nn, 256>>>(A);
    for (int t = 0; t < Tt; t++) {
        scores_kernel<<<dim3(4, Nn), 256>>>(A, x, t);
        attnsum_kernel<<<dim3(4, Nn), 256>>>(t);
        gates_mma_kernel<<<G4 / 32, 256>>>(out, t);
    }
}

// round 7
// speedup vs baseline: 3.1662x; 1.3696x over previous
#include <cuda_runtime.h>
#include <cuda_bf16.h>
#include <math.h>
#include <stdint.h>

#define Nn 128
#define Tt 256
#define Dd 1024
#define Hh 1024
#define G4 4096
#define Pp 196
#define KK 3072   // [x_t | h | attn]

// ================= device scratch (static) =================
__device__ __align__(16) __nv_bfloat16 g_Wfbh[(size_t)G4 * KK];  // Wf^T [j][k] hi
__device__ __align__(16) __nv_bfloat16 g_Wfbl[(size_t)G4 * KK];  // Wf^T [j][k] lo
__device__ __align__(16) __nv_bfloat16 g_acth[(size_t)Nn * KK];  // Act [m][k] hi
__device__ __align__(16) __nv_bfloat16 g_actl[(size_t)Nn * KK];  // Act [m][k] lo
__device__ float g_bf[G4];                    // permuted bias (j' = u*4+g)
__device__ float g_hnewT[Hh * Nn];            // h ping-pong, TRANSPOSED [u][m]
__device__ float g_cT[Hh * Nn];               // cell state, TRANSPOSED [u][m]
__device__ float g_sp[Nn][8][Pp];             // partial scores (8 u-chunks)

// ================= helpers (plain-sm_103-legal) =================
__device__ __forceinline__ uint32_t smem_u32(const void* p) {
    uint32_t a;
    asm("{ .reg .u64 t; cvta.to.shared.u64 t, %1; cvt.u32.u64 %0, t; }" : "=r"(a) : "l"(p));
    return a;
}
__device__ __forceinline__ void cp16(uint32_t dst, const void* src) {
    asm volatile("cp.async.cg.shared.global [%0], [%1], 16;" :: "r"(dst), "l"(src));
}
__device__ __forceinline__ void cpcommit() { asm volatile("cp.async.commit_group;" ::: "memory"); }
template <int N> __device__ __forceinline__ void cpwait() {
    asm volatile("cp.async.wait_group %0;" :: "n"(N) : "memory");
}
__device__ __forceinline__ void ldsm_x4(uint32_t& r0, uint32_t& r1, uint32_t& r2, uint32_t& r3,
                                        uint32_t addr) {
    asm volatile("ldmatrix.sync.aligned.m8n8.x4.shared.b16 {%0,%1,%2,%3}, [%4];"
                 : "=r"(r0), "=r"(r1), "=r"(r2), "=r"(r3) : "r"(addr));
}
__device__ __forceinline__ void mma16816(float* d, const uint32_t* a, const uint32_t* b) {
    asm volatile(
        "mma.sync.aligned.m16n8k16.row.col.f32.bf16.bf16.f32 "
        "{%0,%1,%2,%3}, {%4,%5,%6,%7}, {%8,%9}, {%0,%1,%2,%3};"
        : "+f"(d[0]), "+f"(d[1]), "+f"(d[2]), "+f"(d[3])
        : "r"(a[0]), "r"(a[1]), "r"(a[2]), "r"(a[3]), "r"(b[0]), "r"(b[1]));
}
#define SWZ64(o) ((o) ^ (((o) >> 3) & 0x30))

__device__ __forceinline__ void bf16split(float v, __nv_bfloat16* hi, __nv_bfloat16* lo) {
    __nv_bfloat16 h = __float2bfloat16(v);
    *hi = h;
    *lo = __float2bfloat16(v - __bfloat162float(h));
}

// ================= one-time: permute + split weights to [j][k] bf16 =================
__global__ __launch_bounds__(256) void permute_kernel(
    const float* __restrict__ Wx, const float* __restrict__ Wh,
    const float* __restrict__ Wa, const float* __restrict__ b) {
    size_t total = (size_t)G4 * KK;
    size_t stride = (size_t)gridDim.x * blockDim.x;
    for (size_t idx = (size_t)blockIdx.x * blockDim.x + threadIdx.x; idx < total; idx += stride) {
        int j = (int)(idx / KK);
        int k = (int)(idx - (size_t)j * KK);
        int src = (j & 3) * 1024 + (j >> 2);
        float v;
        if (k < 1024)      v = Wx[(size_t)k * G4 + src];
        else if (k < 2048) v = Wh[(size_t)(k - 1024) * G4 + src];
        else               v = Wa[(size_t)(k - 2048) * G4 + src];
        __nv_bfloat16 hi, lo;
        bf16split(v, &hi, &lo);
        g_Wfbh[idx] = hi;
        g_Wfbl[idx] = lo;
        if (k == 0) g_bf[j] = b[src];
    }
}

// ================= h0 = c0 = mean_p A[n,u,:] =================
__global__ __launch_bounds__(256) void init_kernel(const float* __restrict__ A) {
    int n = blockIdx.x;
    for (int u = threadIdx.x; u < Hh; u += blockDim.x) {
        const float4* r = (const float4*)(A + ((size_t)n * Hh + u) * Pp);
        float s = 0.f;
#pragma unroll
        for (int i = 0; i < 49; i++) {
            float4 v = r[i];
            s += v.x + v.y + v.z + v.w;
        }
        float m = s * (1.f / 196.f);
        g_hnewT[u * Nn + n] = m;
        g_cT[u * Nn + n] = m;
    }
}

// ================= scores partial: grid (8,128); commits x_t + h bf16 splits =================
__global__ __launch_bounds__(256) void scores_kernel(
    const float* __restrict__ A, const float* __restrict__ x, int t) {
    int uc = blockIdx.x, n = blockIdx.y;
    int tid = threadIdx.x;
    int u0 = uc * 128;
    __shared__ float hsh[128];

    if (tid < 128) {
        float hv = g_hnewT[(u0 + tid) * Nn + n];
        float xv = x[((size_t)n * Tt + t) * Dd + u0 + tid];
        __nv_bfloat16 hi, lo;
        bf16split(xv, &hi, &lo);
        g_acth[(size_t)n * KK + u0 + tid] = hi;
        g_actl[(size_t)n * KK + u0 + tid] = lo;
        bf16split(hv, &hi, &lo);
        g_acth[(size_t)n * KK + 1024 + u0 + tid] = hi;
        g_actl[(size_t)n * KK + 1024 + u0 + tid] = lo;
        hsh[tid] = hv;
    }
    __syncthreads();

    if (tid < Pp) {
        const float* ap = A + ((size_t)n * Hh + u0) * Pp + tid;
        float acc = 0.f;
#pragma unroll 8
        for (int u = 0; u < 128; u++) {
            acc += hsh[u] * ap[(size_t)u * Pp];
        }
        g_sp[n][uc][tid] = acc;
    }
}

// ================= attn: softmax + weighted sum (A row-major, L2-hot) =================
__global__ __launch_bounds__(256) void attnsum_kernel(const float* __restrict__ A, int t) {
    int uc = blockIdx.x, n = blockIdx.y;
    int tid = threadIdx.x;
    __shared__ __align__(16) float w[Pp];
    __shared__ float red[256];

    float myscore = 0.f, s = -3.4e38f;
    if (tid < Pp) {
        float acc = 0.f;
#pragma unroll
        for (int q = 0; q < 8; q++) acc += g_sp[n][q][tid];
        myscore = acc * 0.03125f;
        s = myscore;
    }
    red[tid] = s;
    __syncthreads();
    for (int off = 128; off > 0; off >>= 1) {
        if (tid < off) red[tid] = fmaxf(red[tid], red[tid + off]);
        __syncthreads();
    }
    float mx = red[0];
    __syncthreads();
    float e = (tid < Pp) ? expf(myscore - mx) : 0.f;
    red[tid] = e;
    __syncthreads();
    for (int off = 128; off > 0; off >>= 1) {
        if (tid < off) red[tid] += red[tid + off];
        __syncthreads();
    }
    float inv = 1.f / red[0];
    if (tid < Pp) w[tid] = e * inv;
    __syncthreads();

    // attn[u] = A[n,u,:] . w  (contiguous 784B row per thread, A hot in L2)
    int u = uc * 256 + tid;
    const float4* Ar = (const float4*)(A + ((size_t)n * Hh + u) * Pp);
    float acc = 0.f;
#pragma unroll
    for (int i = 0; i < 49; i++) {
        float4 av = Ar[i];
        float4 wv = *(const float4*)&w[4 * i];
        acc += av.x * wv.x + av.y * wv.y + av.z * wv.z + av.w * wv.w;
    }
    __nv_bfloat16 hi, lo;
    bf16split(acc, &hi, &lo);
    g_acth[(size_t)n * KK + 2048 + u] = hi;
    g_actl[(size_t)n * KK + 2048 + u] = lo;
}

// ================= gates: mma.sync split-bf16x3 GEMM + fused LSTM =================
// grid 128 (32 cols each), 256 threads (8 warps x 16 rows). K chunks of 32.
// 3-stage cp.async ring, ONE syncthreads per chunk.
// Stage layout: Ah[0,8K) Al[8K,16K) Bh[16K,18K) Bl[18K,20K).
#define KC 32
#define NCH (KK / KC)   // 96
#define STB 20480
#define NSTG 3

__device__ __forceinline__ void load_chunk(int tid, int j0, int c, char* buf) {
    uint32_t sbase = smem_u32(buf);
#pragma unroll
    for (int it = 0; it < 2; it++) {
        int id = tid + it * 256;          // 0..511 : A rows x 4 16B-chunks
        int m = id >> 2, kc = id & 3;
        uint32_t off = SWZ64((uint32_t)m * 64 + (uint32_t)kc * 16);
        size_t gidx = (size_t)m * KK + (size_t)c * KC + kc * 8;
        cp16(sbase + off, g_acth + gidx);
        cp16(sbase + 8192 + off, g_actl + gidx);
    }
    if (tid < 128) {
        int nrow = tid >> 2, kc = tid & 3;
        uint32_t off = SWZ64((uint32_t)nrow * 64 + (uint32_t)kc * 16);
        size_t gidx = (size_t)(j0 + nrow) * KK + (size_t)c * KC + kc * 8;
        cp16(sbase + 16384 + off, g_Wfbh + gidx);
        cp16(sbase + 18432 + off, g_Wfbl + gidx);
    }
    cpcommit();
}

__global__ __launch_bounds__(256) void gates_mma_kernel(float* __restrict__ out, int t) {
    extern __shared__ __align__(1024) char dsm[];
    int tid = threadIdx.x;
    int w = tid >> 5;
    int lane = tid & 31;
    int j0 = blockIdx.x * 32;

    float acc[4][4];
#pragma unroll
    for (int j = 0; j < 4; j++)
#pragma unroll
        for (int r = 0; r < 4; r++) acc[j][r] = 0.f;

    load_chunk(tid, j0, 0, dsm);
    load_chunk(tid, j0, 1, dsm + STB);

    for (int c = 0; c < NCH; c++) {
        if (c + 1 < NCH) cpwait<1>(); else cpwait<0>();
        __syncthreads();

        uint32_t sbase = smem_u32(dsm + (c % NSTG) * STB);
        int arow = w * 16 + (lane & 15);
#pragma unroll
        for (int ks = 0; ks < 2; ks++) {
            int ak = ks * 16 + ((lane & 16) ? 8 : 0);
            uint32_t aoff = SWZ64((uint32_t)arow * 64 + (uint32_t)ak * 2);
            uint32_t ah[4], al[4];
            ldsm_x4(ah[0], ah[1], ah[2], ah[3], sbase + aoff);
            ldsm_x4(al[0], al[1], al[2], al[3], sbase + 8192 + aoff);

            uint32_t bh[8], bl[8];
            int bk = ks * 16 + ((lane & 8) ? 8 : 0);
#pragma unroll
            for (int jj = 0; jj < 2; jj++) {
                int nrow = jj * 16 + ((lane & 16) ? 8 : 0) + (lane & 7);
                uint32_t boff = SWZ64((uint32_t)nrow * 64 + (uint32_t)bk * 2);
                ldsm_x4(bh[4 * jj], bh[4 * jj + 1], bh[4 * jj + 2], bh[4 * jj + 3],
                        sbase + 16384 + boff);
                ldsm_x4(bl[4 * jj], bl[4 * jj + 1], bl[4 * jj + 2], bl[4 * jj + 3],
                        sbase + 18432 + boff);
            }
#pragma unroll
            for (int j = 0; j < 4; j++) {
                mma16816(acc[j], ah, &bh[2 * j]);
                mma16816(acc[j], ah, &bl[2 * j]);
                mma16816(acc[j], al, &bh[2 * j]);
            }
        }
        // issue chunk c+2 AFTER compute: writes buf (c+2)%3 != (c)%3, and
        // everyone passed the sync above, so no warp is still reading it.
        if (c + 2 < NCH) load_chunk(tid, j0, c + 2, dsm + ((c + 2) % NSTG) * STB);
    }

    // ---- fused LSTM epilogue ----
    int q = lane & 3;
    int rbase = w * 16 + (lane >> 2);
#pragma unroll
    for (int j = 0; j < 4; j++) {
        float e0 = __shfl_xor_sync(0xffffffff, acc[j][0], 1);
        float e1 = __shfl_xor_sync(0xffffffff, acc[j][1], 1);
        float e2 = __shfl_xor_sync(0xffffffff, acc[j][2], 1);
        float e3 = __shfl_xor_sync(0xffffffff, acc[j][3], 1);
        int u = blockIdx.x * 8 + 2 * j + (q >> 1);
        int m;
        float ai, af, ao, ag;
        if ((q & 1) == 0) {
            m = rbase;
            ai = acc[j][0]; af = acc[j][1]; ao = e0; ag = e1;
        } else {
            m = rbase + 8;
            ai = e2; af = e3; ao = acc[j][2]; ag = acc[j][3];
        }
        float4 bb = *(const float4*)&g_bf[u * 4];
        ai += bb.x; af += bb.y; ao += bb.z; ag += bb.w;
        float ig = 1.f / (1.f + expf(-ai));
        float fg = 1.f / (1.f + expf(-af));
        float og = 1.f / (1.f + expf(-ao));
        float gg = tanhf(ag);
        float cn = fg * g_cT[u * Nn + m] + ig * gg;
        float hn = og * tanhf(cn);
        g_cT[u * Nn + m] = cn;
        g_hnewT[u * Nn + m] = hn;
        out[((size_t)m * Tt + t) * Hh + u] = hn;
    }
}

extern "C" void kernel_launch(void* const* d_in, const int* in_sizes, int n_in,
                              void* d_out, int out_size) {
    const float* x  = (const float*)d_in[0];
    const float* A  = (const float*)d_in[1];
    const float* Wx = (const float*)d_in[2];
    const float* Wh = (const float*)d_in[3];
    const float* Wa = (const float*)d_in[4];
    const float* b  = (const float*)d_in[5];
    float* out = (float*)d_out;

    cudaFuncSetAttribute(gates_mma_kernel, cudaFuncAttributeMaxDynamicSharedMemorySize,
                         NSTG * STB);

    permute_kernel<<<2048, 256>>>(Wx, Wh, Wa, b);
    init_kernel<<<Nn, 256>>>(A);
    for (int t = 0; t < Tt; t++) {
        scores_kernel<<<dim3(8, Nn), 256>>>(A, x, t);
        attnsum_kernel<<<dim3(4, Nn), 256>>>(A, t);
        gates_mma_kernel<<<G4 / 32, 256, NSTG * STB>>>(out, t);
    }
}

// round 9
// speedup vs baseline: 3.5788x; 1.1303x over previous
#include <cuda_runtime.h>
#include <cuda_bf16.h>
#include <math.h>
#include <stdint.h>

#define Nn 128
#define Tt 256
#define Dd 1024
#define Hh 1024
#define G4 4096
#define Pp 196
#define KR 2048   // recurrent K: [h | attn]
#define MX (Nn * Tt)   // 32768 xproj rows

// ================= device scratch (static) =================
__device__ __align__(16) __nv_bfloat16 g_Wxh[(size_t)G4 * Dd];   // Wx^T [j'][k] hi
__device__ __align__(16) __nv_bfloat16 g_Wxl[(size_t)G4 * Dd];   // Wx^T [j'][k] lo
__device__ __align__(16) __nv_bfloat16 g_Wfh[(size_t)G4 * KR];   // [Wh;Wattn]^T [j'][k] hi
__device__ __align__(16) __nv_bfloat16 g_Wfl[(size_t)G4 * KR];   // lo
__device__ __align__(16) __nv_bfloat16 g_xh[(size_t)MX * Dd];    // x split hi  [n*Tt+t][d]
__device__ __align__(16) __nv_bfloat16 g_xl[(size_t)MX * Dd];    // x split lo
__device__ float g_xp[(size_t)MX * G4];                          // xproj = x@Wx + b
__device__ __align__(16) __nv_bfloat16 g_acth[(size_t)Nn * KR];  // [h | attn] hi
__device__ __align__(16) __nv_bfloat16 g_actl[(size_t)Nn * KR];  // lo
__device__ float g_bf[G4];                    // permuted bias
__device__ float g_hnewT[Hh * Nn];            // h ping-pong, [u][m]
__device__ float g_cT[Hh * Nn];               // cell state, [u][m]
__device__ float g_sp[Nn][8][Pp];             // partial scores

// ================= helpers (plain-sm_103-legal, R6-proven set only) =================
__device__ __forceinline__ uint32_t smem_u32(const void* p) {
    uint32_t a;
    asm("{ .reg .u64 t; cvta.to.shared.u64 t, %1; cvt.u32.u64 %0, t; }" : "=r"(a) : "l"(p));
    return a;
}
__device__ __forceinline__ void cp16(uint32_t dst, const void* src) {
    asm volatile("cp.async.cg.shared.global [%0], [%1], 16;" :: "r"(dst), "l"(src));
}
__device__ __forceinline__ void cpcommit() { asm volatile("cp.async.commit_group;" ::: "memory"); }
template <int N> __device__ __forceinline__ void cpwait() {
    asm volatile("cp.async.wait_group %0;" :: "n"(N) : "memory");
}
__device__ __forceinline__ void ldsm_x4(uint32_t& r0, uint32_t& r1, uint32_t& r2, uint32_t& r3,
                                        uint32_t addr) {
    asm volatile("ldmatrix.sync.aligned.m8n8.x4.shared.b16 {%0,%1,%2,%3}, [%4];"
                 : "=r"(r0), "=r"(r1), "=r"(r2), "=r"(r3) : "r"(addr));
}
__device__ __forceinline__ void mma16816(float* d, const uint32_t* a, const uint32_t* b) {
    asm volatile(
        "mma.sync.aligned.m16n8k16.row.col.f32.bf16.bf16.f32 "
        "{%0,%1,%2,%3}, {%4,%5,%6,%7}, {%8,%9}, {%0,%1,%2,%3};"
        : "+f"(d[0]), "+f"(d[1]), "+f"(d[2]), "+f"(d[3])
        : "r"(a[0]), "r"(a[1]), "r"(a[2]), "r"(a[3]), "r"(b[0]), "r"(b[1]));
}
#define SWZ64(o) ((o) ^ (((o) >> 3) & 0x30))

__device__ __forceinline__ void bf16split(float v, __nv_bfloat16* hi, __nv_bfloat16* lo) {
    __nv_bfloat16 h = __float2bfloat16(v);
    *hi = h;
    *lo = __float2bfloat16(v - __bfloat162float(h));
}

// ================= one-time kernels =================
__global__ __launch_bounds__(256) void permute_kernel(
    const float* __restrict__ Wx, const float* __restrict__ Wh,
    const float* __restrict__ Wa, const float* __restrict__ b) {
    size_t total = (size_t)G4 * 3072;
    size_t stride = (size_t)gridDim.x * blockDim.x;
    for (size_t idx = (size_t)blockIdx.x * blockDim.x + threadIdx.x; idx < total; idx += stride) {
        int j = (int)(idx / 3072);
        int k = (int)(idx - (size_t)j * 3072);
        int src = (j & 3) * 1024 + (j >> 2);
        __nv_bfloat16 hi, lo;
        if (k < 1024) {
            bf16split(Wx[(size_t)k * G4 + src], &hi, &lo);
            g_Wxh[(size_t)j * Dd + k] = hi;
            g_Wxl[(size_t)j * Dd + k] = lo;
        } else {
            float v = (k < 2048) ? Wh[(size_t)(k - 1024) * G4 + src]
                                 : Wa[(size_t)(k - 2048) * G4 + src];
            bf16split(v, &hi, &lo);
            g_Wfh[(size_t)j * KR + (k - 1024)] = hi;
            g_Wfl[(size_t)j * KR + (k - 1024)] = lo;
        }
        if (k == 0) g_bf[j] = b[src];
    }
}

__global__ __launch_bounds__(256) void xsplit_kernel(const float* __restrict__ x) {
    size_t total = (size_t)MX * Dd;
    size_t stride = (size_t)gridDim.x * blockDim.x;
    for (size_t i = (size_t)blockIdx.x * blockDim.x + threadIdx.x; i < total; i += stride) {
        __nv_bfloat16 hi, lo;
        bf16split(x[i], &hi, &lo);
        g_xh[i] = hi;
        g_xl[i] = lo;
    }
}

__global__ __launch_bounds__(256) void init_kernel(const float* __restrict__ A) {
    int n = blockIdx.x;
    for (int u = threadIdx.x; u < Hh; u += blockDim.x) {
        const float4* r = (const float4*)(A + ((size_t)n * Hh + u) * Pp);
        float s = 0.f;
#pragma unroll
        for (int i = 0; i < 49; i++) {
            float4 v = r[i];
            s += v.x + v.y + v.z + v.w;
        }
        float m = s * (1.f / 196.f);
        g_hnewT[u * Nn + n] = m;
        g_cT[u * Nn + n] = m;
    }
}

// ================= generic split-bf16x3 mma mainloop =================
#define KC 32
#define STB 20480
#define NSTG 3

__device__ __forceinline__ void load_chunk_g(
    int tid, int c, char* buf,
    const __nv_bfloat16* Ah, const __nv_bfloat16* Al, int lda,
    const __nv_bfloat16* Bh, const __nv_bfloat16* Bl, int ldb) {
    uint32_t sbase = smem_u32(buf);
#pragma unroll
    for (int it = 0; it < 2; it++) {
        int id = tid + it * 256;
        int m = id >> 2, kc = id & 3;
        uint32_t off = SWZ64((uint32_t)m * 64 + (uint32_t)kc * 16);
        size_t gidx = (size_t)m * lda + (size_t)c * KC + kc * 8;
        cp16(sbase + off, Ah + gidx);
        cp16(sbase + 8192 + off, Al + gidx);
    }
    if (tid < 128) {
        int nrow = tid >> 2, kc = tid & 3;
        uint32_t off = SWZ64((uint32_t)nrow * 64 + (uint32_t)kc * 16);
        size_t gidx = (size_t)nrow * ldb + (size_t)c * KC + kc * 8;
        cp16(sbase + 16384 + off, Bh + gidx);
        cp16(sbase + 18432 + off, Bl + gidx);
    }
    cpcommit();
}

__device__ __forceinline__ void mma_mainloop(
    int tid, char* dsm, float acc[4][4], int nch,
    const __nv_bfloat16* Ah, const __nv_bfloat16* Al, int lda,
    const __nv_bfloat16* Bh, const __nv_bfloat16* Bl, int ldb) {
    int w = tid >> 5, lane = tid & 31;
    load_chunk_g(tid, 0, dsm, Ah, Al, lda, Bh, Bl, ldb);
    load_chunk_g(tid, 1, dsm + STB, Ah, Al, lda, Bh, Bl, ldb);
    for (int c = 0; c < nch; c++) {
        if (c + 1 < nch) cpwait<1>(); else cpwait<0>();
        __syncthreads();
        uint32_t sbase = smem_u32(dsm + (c % NSTG) * STB);
        int arow = w * 16 + (lane & 15);
#pragma unroll
        for (int ks = 0; ks < 2; ks++) {
            int ak = ks * 16 + ((lane & 16) ? 8 : 0);
            uint32_t aoff = SWZ64((uint32_t)arow * 64 + (uint32_t)ak * 2);
            uint32_t ah[4], al[4];
            ldsm_x4(ah[0], ah[1], ah[2], ah[3], sbase + aoff);
            ldsm_x4(al[0], al[1], al[2], al[3], sbase + 8192 + aoff);
            uint32_t bh[8], bl[8];
            int bk = ks * 16 + ((lane & 8) ? 8 : 0);
#pragma unroll
            for (int jj = 0; jj < 2; jj++) {
                int nrow = jj * 16 + ((lane & 16) ? 8 : 0) + (lane & 7);
                uint32_t boff = SWZ64((uint32_t)nrow * 64 + (uint32_t)bk * 2);
                ldsm_x4(bh[4 * jj], bh[4 * jj + 1], bh[4 * jj + 2], bh[4 * jj + 3],
                        sbase + 16384 + boff);
                ldsm_x4(bl[4 * jj], bl[4 * jj + 1], bl[4 * jj + 2], bl[4 * jj + 3],
                        sbase + 18432 + boff);
            }
#pragma unroll
            for (int j = 0; j < 4; j++) {
                mma16816(acc[j], ah, &bh[2 * j]);
                mma16816(acc[j], ah, &bl[2 * j]);
                mma16816(acc[j], al, &bh[2 * j]);
            }
        }
        if (c + 2 < nch)
            load_chunk_g(tid, c + 2, dsm + ((c + 2) % NSTG) * STB, Ah, Al, lda, Bh, Bl, ldb);
    }
}

// ================= one-time: xproj = x @ Wx + b =================
__global__ __launch_bounds__(256) void xproj_kernel() {
    extern __shared__ __align__(1024) char dsm[];
    int tid = threadIdx.x;
    int w = tid >> 5, lane = tid & 31;
    int j0 = blockIdx.x * 32;
    int m0 = blockIdx.y * 128;

    float acc[4][4];
#pragma unroll
    for (int j = 0; j < 4; j++)
#pragma unroll
        for (int r = 0; r < 4; r++) acc[j][r] = 0.f;

    mma_mainloop(tid, dsm, acc, Dd / KC,
                 g_xh + (size_t)m0 * Dd, g_xl + (size_t)m0 * Dd, Dd,
                 g_Wxh + (size_t)j0 * Dd, g_Wxl + (size_t)j0 * Dd, Dd);

    int row0 = m0 + w * 16 + (lane >> 2);
#pragma unroll
    for (int j = 0; j < 4; j++) {
        int col = j0 + j * 8 + (lane & 3) * 2;
        float2 bb = *(const float2*)&g_bf[col];
        *(float2*)&g_xp[(size_t)row0 * G4 + col] = make_float2(acc[j][0] + bb.x, acc[j][1] + bb.y);
        *(float2*)&g_xp[(size_t)(row0 + 8) * G4 + col] = make_float2(acc[j][2] + bb.x, acc[j][3] + bb.y);
    }
}

// ================= scores partial: grid (8,128); commits h bf16 split =================
__global__ __launch_bounds__(256) void scores_kernel(const float* __restrict__ A, int t) {
    int uc = blockIdx.x, n = blockIdx.y;
    int tid = threadIdx.x;
    int u0 = uc * 128;
    __shared__ float hsh[128];

    if (tid < 128) {
        float hv = g_hnewT[(u0 + tid) * Nn + n];
        __nv_bfloat16 hi, lo;
        bf16split(hv, &hi, &lo);
        g_acth[(size_t)n * KR + u0 + tid] = hi;
        g_actl[(size_t)n * KR + u0 + tid] = lo;
        hsh[tid] = hv;
    }
    __syncthreads();

    if (tid < Pp) {
        const float* ap = A + ((size_t)n * Hh + u0) * Pp + tid;
        float acc = 0.f;
#pragma unroll 8
        for (int u = 0; u < 128; u++) {
            acc += hsh[u] * ap[(size_t)u * Pp];
        }
        g_sp[n][uc][tid] = acc;
    }
}

// ================= attn: softmax + weighted sum (n reversed for L2 reuse) =================
__global__ __launch_bounds__(256) void attnsum_kernel(const float* __restrict__ A, int t) {
    int uc = blockIdx.x;
    int n = (Nn - 1) - blockIdx.y;   // reverse sweep: chase scores' warm L2 lines
    int tid = threadIdx.x;
    __shared__ __align__(16) float w[Pp];
    __shared__ float red[256];

    float myscore = 0.f, s = -3.4e38f;
    if (tid < Pp) {
        float acc = 0.f;
#pragma unroll
        for (int q = 0; q < 8; q++) acc += g_sp[n][q][tid];
        myscore = acc * 0.03125f;
        s = myscore;
    }
    red[tid] = s;
    __syncthreads();
    for (int off = 128; off > 0; off >>= 1) {
        if (tid < off) red[tid] = fmaxf(red[tid], red[tid + off]);
        __syncthreads();
    }
    float mx = red[0];
    __syncthreads();
    float e = (tid < Pp) ? expf(myscore - mx) : 0.f;
    red[tid] = e;
    __syncthreads();
    for (int off = 128; off > 0; off >>= 1) {
        if (tid < off) red[tid] += red[tid + off];
        __syncthreads();
    }
    float inv = 1.f / red[0];
    if (tid < Pp) w[tid] = e * inv;
    __syncthreads();

    int u = uc * 256 + tid;
    const float4* Ar = (const float4*)(A + ((size_t)n * Hh + u) * Pp);
    float acc = 0.f;
#pragma unroll
    for (int i = 0; i < 49; i++) {
        float4 av = Ar[i];
        float4 wv = *(const float4*)&w[4 * i];
        acc += av.x * wv.x + av.y * wv.y + av.z * wv.z + av.w * wv.w;
    }
    __nv_bfloat16 hi, lo;
    bf16split(acc, &hi, &lo);
    g_acth[(size_t)n * KR + 1024 + u] = hi;
    g_actl[(size_t)n * KR + 1024 + u] = lo;
}

// ================= gates: [h|attn]@Wf + xproj_t, fused LSTM =================
__global__ __launch_bounds__(256) void gates_mma_kernel(float* __restrict__ out, int t) {
    extern __shared__ __align__(1024) char dsm[];
    int tid = threadIdx.x;
    int w = tid >> 5, lane = tid & 31;
    int j0 = blockIdx.x * 32;

    // init accumulators from xproj (streaming loads)
    float acc[4][4];
    {
        int row0 = w * 16 + (lane >> 2);
#pragma unroll
        for (int j = 0; j < 4; j++) {
            int col = j0 + j * 8 + (lane & 3) * 2;
            float2 v0 = __ldcs((const float2*)&g_xp[((size_t)row0 * Tt + t) * G4 + col]);
            float2 v1 = __ldcs((const float2*)&g_xp[((size_t)(row0 + 8) * Tt + t) * G4 + col]);
            acc[j][0] = v0.x; acc[j][1] = v0.y; acc[j][2] = v1.x; acc[j][3] = v1.y;
        }
    }

    mma_mainloop(tid, dsm, acc, KR / KC,
                 g_acth, g_actl, KR,
                 g_Wfh + (size_t)j0 * KR, g_Wfl + (size_t)j0 * KR, KR);

    // ---- fused LSTM epilogue ----
    int q = lane & 3;
    int rbase = w * 16 + (lane >> 2);
#pragma unroll
    for (int j = 0; j < 4; j++) {
        float e0 = __shfl_xor_sync(0xffffffff, acc[j][0], 1);
        float e1 = __shfl_xor_sync(0xffffffff, acc[j][1], 1);
        float e2 = __shfl_xor_sync(0xffffffff, acc[j][2], 1);
        float e3 = __shfl_xor_sync(0xffffffff, acc[j][3], 1);
        int u = blockIdx.x * 8 + 2 * j + (q >> 1);
        int m;
        float ai, af, ao, ag;
        if ((q & 1) == 0) {
            m = rbase;
            ai = acc[j][0]; af = acc[j][1]; ao = e0; ag = e1;
        } else {
            m = rbase + 8;
            ai = e2; af = e3; ao = acc[j][2]; ag = acc[j][3];
        }
        float ig = 1.f / (1.f + expf(-ai));
        float fg = 1.f / (1.f + expf(-af));
        float og = 1.f / (1.f + expf(-ao));
        float gg = tanhf(ag);
        float cn = fg * g_cT[u * Nn + m] + ig * gg;
        float hn = og * tanhf(cn);
        g_cT[u * Nn + m] = cn;
        g_hnewT[u * Nn + m] = hn;
        __stcs(&out[((size_t)m * Tt + t) * Hh + u], hn);
    }
}

extern "C" void kernel_launch(void* const* d_in, const int* in_sizes, int n_in,
                              void* d_out, int out_size) {
    const float* x  = (const float*)d_in[0];
    const float* A  = (const float*)d_in[1];
    const float* Wx = (const float*)d_in[2];
    const float* Wh = (const float*)d_in[3];
    const float* Wa = (const float*)d_in[4];
    const float* b  = (const float*)d_in[5];
    float* out = (float*)d_out;

    cudaFuncSetAttribute(gates_mma_kernel, cudaFuncAttributeMaxDynamicSharedMemorySize, NSTG * STB);
    cudaFuncSetAttribute(xproj_kernel, cudaFuncAttributeMaxDynamicSharedMemorySize, NSTG * STB);

    permute_kernel<<<2048, 256>>>(Wx, Wh, Wa, b);
    xsplit_kernel<<<4096, 256>>>(x);
    init_kernel<<<Nn, 256>>>(A);
    xproj_kernel<<<dim3(G4 / 32, MX / 128), 256, NSTG * STB>>>();
    for (int t = 0; t < Tt; t++) {
        scores_kernel<<<dim3(8, Nn), 256>>>(A, t);
        attnsum_kernel<<<dim3(4, Nn), 256>>>(A, t);
        gates_mma_kernel<<<G4 / 32, 256, NSTG * STB>>>(out, t);
    }
}